// round 9
// baseline (speedup 1.0000x reference)
#include <cuda_runtime.h>
#include <math.h>

// Problem constants
#define B_ 256
#define R_ 1152
#define C_ 10
#define O_ 16
#define I_ 8
#define RT_ 4                 // r's per tile
#define RPC_ (R_/RT_)         // 288 tiles per c
#define NT_ (RPC_*C_)         // 2880 tiles total
#define G0_ 888               // pass0 grid: 148 x 6 -> one wave
#define G12_ 592              // pass1/2 grid: 148 x 4 -> one wave

// ---------------- device scratch (no allocations allowed) ----------------
__device__ float g_xT[R_*B_*I_];       // x transposed: [r][b][i]   (9.4 MB)
__device__ float g_Wp[R_*C_*I_*O_];    // W reformatted: [r][c][i][o] (5.9 MB)
__device__ float g_b1[R_*C_*B_];       // routing logits b1: [r][c][b] (11.8 MB)
__device__ float g_S[C_*O_*B_];        // numerator accumulator: [c][o][b]
__device__ float g_E[C_*B_];           // softmax denominator:   [c][b]
__device__ float g_v[B_*C_*O_];        // squashed v: [b][c][o]

typedef unsigned long long u64;

// ---------------- packed f32x2 helpers (Blackwell FFMA2) ----------------
__device__ __forceinline__ u64 pk2(float lo, float hi){
    u64 r; asm("mov.b64 %0,{%1,%2};" : "=l"(r) : "f"(lo), "f"(hi)); return r;
}
__device__ __forceinline__ void upk2(u64 v, float& lo, float& hi){
    asm("mov.b64 {%0,%1},%2;" : "=f"(lo), "=f"(hi) : "l"(v));
}
__device__ __forceinline__ u64 ffma2(u64 a, u64 b, u64 c){
    u64 d; asm("fma.rn.f32x2 %0,%1,%2,%3;" : "=l"(d) : "l"(a), "l"(b), "l"(c)); return d;
}
__device__ __forceinline__ u64 fadd2(u64 a, u64 b){
    u64 d; asm("add.rn.f32x2 %0,%1,%2;" : "=l"(d) : "l"(a), "l"(b)); return d;
}

// ---------------- combined prep kernel ----------------
#define XT_BLOCKS 288            // 36 r-tiles x 8 b-tiles
#define PREP_BLOCKS (XT_BLOCKS + 720)

__global__ void __launch_bounds__(256) prep_kernel(const float* __restrict__ x,
                                                   const float* __restrict__ W){
    if (blockIdx.x < XT_BLOCKS){
        __shared__ __align__(16) float4 p0[32][33];
        __shared__ __align__(16) float4 p1[32][33];
        const int rt = blockIdx.x >> 3, bt = blockIdx.x & 7;
        const int r0 = rt*32, b0 = bt*32;
        const int w = threadIdx.x >> 5, lane = threadIdx.x & 31;

#pragma unroll
        for (int k = 0; k < 4; k++){
            int bl = w*4 + k;
            const float4* src = reinterpret_cast<const float4*>(
                x + ((b0+bl)*R_ + r0 + lane)*I_);
            p0[bl][lane] = src[0];
            p1[bl][lane] = src[1];
        }
        __syncthreads();
#pragma unroll
        for (int k = 0; k < 4; k++){
            int rl = w*4 + k;
            float4* dst = reinterpret_cast<float4*>(
                g_xT + ((r0+rl)*B_ + b0 + lane)*I_);
            dst[0] = p0[lane][rl];
            dst[1] = p1[lane][rl];
        }
    } else {
        int t = (blockIdx.x - XT_BLOCKS)*256 + threadIdx.x;   // over R_*C_*O_
        int o = t % O_; int rc = t / O_;
        const float* src = W + t*I_;                          // W[rc][o][0..7]
        float* dst = g_Wp + rc*(I_*O_);
#pragma unroll
        for (int i = 0; i < I_; i++) dst[i*O_ + o] = src[i];

        if (t < C_*O_*B_) g_S[t] = 0.f;
        if (t < C_*B_)    g_E[t] = 0.f;
    }
}

// ---------------- shared helpers for passes ----------------
__device__ __forceinline__ void flush_S(int c, int b0, int b1,
                                        const u64* Sa, const u64* Sb,
                                        float Ea, float Eb, int mode){
#pragma unroll
    for (int j = 0; j < 8; j++){
        float lo, hi;
        upk2(Sa[j], lo, hi);
        atomicAdd(&g_S[(c*O_ + 2*j    )*B_ + b0], lo);
        atomicAdd(&g_S[(c*O_ + 2*j + 1)*B_ + b0], hi);
        upk2(Sb[j], lo, hi);
        atomicAdd(&g_S[(c*O_ + 2*j    )*B_ + b1], lo);
        atomicAdd(&g_S[(c*O_ + 2*j + 1)*B_ + b1], hi);
    }
    if (mode){
        atomicAdd(&g_E[c*B_ + b0], Ea);
        atomicAdd(&g_E[c*B_ + b1], Eb);
    }
}

// compute u for both b's from staged W row + x registers
__device__ __forceinline__ void compute_u(const float* wrow,
                                          const float4& xa0, const float4& xa1,
                                          const float4& xb0, const float4& xb1,
                                          u64* ua, u64* ub){
    const float xsa[8] = {xa0.x, xa0.y, xa0.z, xa0.w, xa1.x, xa1.y, xa1.z, xa1.w};
    const float xsb[8] = {xb0.x, xb0.y, xb0.z, xb0.w, xb1.x, xb1.y, xb1.z, xb1.w};
#pragma unroll
    for (int j = 0; j < 8; j++){ ua[j] = 0ull; ub[j] = 0ull; }
#pragma unroll
    for (int i = 0; i < I_; i++){
        u64 xda = pk2(xsa[i], xsa[i]);
        u64 xdb = pk2(xsb[i], xsb[i]);
        const ulonglong2* wp = reinterpret_cast<const ulonglong2*>(wrow + i*O_);
#pragma unroll
        for (int jj = 0; jj < 4; jj++){
            ulonglong2 ww = wp[jj];               // LDS.128 broadcast, shared by both b's
            ua[2*jj]   = ffma2(ww.x, xda, ua[2*jj]);
            ua[2*jj+1] = ffma2(ww.y, xda, ua[2*jj+1]);
            ub[2*jj]   = ffma2(ww.x, xdb, ub[2*jj]);
            ub[2*jj+1] = ffma2(ww.y, xdb, ub[2*jj+1]);
        }
    }
}

// ---------------- pass 0: S += u_hat (uniform coupling) ----------------
// low registers -> 6 blocks/SM, grid 888, one wave
__global__ void __launch_bounds__(128, 6) pass0_kernel(){
    __shared__ __align__(16) float4 Ws[2][RT_*32];
    const int k   = blockIdx.x;
    const int t0  = (k    * NT_) / G0_;
    const int t1  = ((k+1)* NT_) / G0_;
    const int tid = threadIdx.x;
    const int b0  = tid, b1 = tid + 128;
    const int srl = tid >> 5, sw = tid & 31;

    u64 Sa[8], Sb[8];
    int cur_c = -1;
    int p = 0;

#pragma unroll 1
    for (int t = t0; t < t1; t++){
        const int c  = t / RPC_;
        const int r0 = (t % RPC_) * RT_;

        if (c != cur_c){
            if (cur_c >= 0) flush_S(cur_c, b0, b1, Sa, Sb, 0.f, 0.f, 0);
#pragma unroll
            for (int j = 0; j < 8; j++){ Sa[j] = 0ull; Sb[j] = 0ull; }
            cur_c = c;
        }

        Ws[p][srl*32 + sw] =
            reinterpret_cast<const float4*>(g_Wp)[((r0+srl)*C_ + c)*32 + sw];
        __syncthreads();

#pragma unroll
        for (int rl = 0; rl < RT_; rl++){
            const int r = r0 + rl;
            const float4* pa = reinterpret_cast<const float4*>(g_xT + (r*B_ + b0)*I_);
            const float4* pb = reinterpret_cast<const float4*>(g_xT + (r*B_ + b1)*I_);
            float4 xa0 = pa[0], xa1 = pa[1], xb0 = pb[0], xb1 = pb[1];

            u64 ua[8], ub[8];
            compute_u(reinterpret_cast<const float*>(&Ws[p][rl*32]),
                      xa0, xa1, xb0, xb1, ua, ub);
#pragma unroll
            for (int j = 0; j < 8; j++){
                Sa[j] = fadd2(Sa[j], ua[j]);
                Sb[j] = fadd2(Sb[j], ub[j]);
            }
        }
        p ^= 1;
    }
    if (cur_c >= 0) flush_S(cur_c, b0, b1, Sa, Sb, 0.f, 0.f, 0);
}

// ---------------- passes 1/2 (softmax-weighted) ----------------
// MODE 1: b1 = u.v0 (store), S += e*u, E += e,  e = exp(b1)
// MODE 2: b2 = b1 + u.v1,    S += e*u, E += e,  e = exp(b2)
// register cap 128 -> 4 blocks/SM, grid 592, one wave
template<int MODE>
__global__ void __launch_bounds__(128, 4) pass_kernel(){
    __shared__ __align__(16) float4 Ws[2][RT_*32];
    const int k   = blockIdx.x;
    const int t0  = (k    * NT_) / G12_;
    const int t1  = ((k+1)* NT_) / G12_;
    const int tid = threadIdx.x;
    const int b0  = tid, b1 = tid + 128;
    const int srl = tid >> 5, sw = tid & 31;

    u64 Sa[8], Sb[8], va[8], vb[8];
    float Ea = 0.f, Eb = 0.f;
    int cur_c = -1;
    int p = 0;

#pragma unroll 1
    for (int t = t0; t < t1; t++){
        const int c  = t / RPC_;
        const int r0 = (t % RPC_) * RT_;

        if (c != cur_c){
            if (cur_c >= 0) flush_S(cur_c, b0, b1, Sa, Sb, Ea, Eb, 1);
#pragma unroll
            for (int j = 0; j < 8; j++){ Sa[j] = 0ull; Sb[j] = 0ull; }
            Ea = 0.f; Eb = 0.f;
            const float4* vpa = reinterpret_cast<const float4*>(g_v + (b0*C_ + c)*O_);
            const float4* vpb = reinterpret_cast<const float4*>(g_v + (b1*C_ + c)*O_);
#pragma unroll
            for (int q = 0; q < 4; q++){
                float4 f = vpa[q]; va[2*q] = pk2(f.x, f.y); va[2*q+1] = pk2(f.z, f.w);
                float4 g = vpb[q]; vb[2*q] = pk2(g.x, g.y); vb[2*q+1] = pk2(g.z, g.w);
            }
            cur_c = c;
        }

        Ws[p][srl*32 + sw] =
            reinterpret_cast<const float4*>(g_Wp)[((r0+srl)*C_ + c)*32 + sw];
        __syncthreads();

#pragma unroll
        for (int rl = 0; rl < RT_; rl++){
            const int r = r0 + rl;
            const float4* pa = reinterpret_cast<const float4*>(g_xT + (r*B_ + b0)*I_);
            const float4* pb = reinterpret_cast<const float4*>(g_xT + (r*B_ + b1)*I_);
            float4 xa0 = pa[0], xa1 = pa[1], xb0 = pb[0], xb1 = pb[1];

            u64 ua[8], ub[8];
            compute_u(reinterpret_cast<const float*>(&Ws[p][rl*32]),
                      xa0, xa1, xb0, xb1, ua, ub);

            // t = <u, v>  (4 independent chains)
            u64 q0 = 0ull, q1 = 0ull, q2 = 0ull, q3 = 0ull;
#pragma unroll
            for (int j = 0; j < 4; j++){
                q0 = ffma2(ua[2*j],   va[2*j],   q0);
                q1 = ffma2(ua[2*j+1], va[2*j+1], q1);
                q2 = ffma2(ub[2*j],   vb[2*j],   q2);
                q3 = ffma2(ub[2*j+1], vb[2*j+1], q3);
            }
            float l, h, ta, tb_;
            upk2(fadd2(q0, q1), l, h); ta  = l + h;
            upk2(fadd2(q2, q3), l, h); tb_ = l + h;

            const int bidx = (r*C_ + c)*B_ + b0;
            if (MODE == 2){ ta += g_b1[bidx]; tb_ += g_b1[bidx + 128]; }
            else          { g_b1[bidx] = ta;  g_b1[bidx + 128] = tb_;  }

            float ea = __expf(ta), eb = __expf(tb_);
            Ea += ea; Eb += eb;
            u64 eda = pk2(ea, ea), edb = pk2(eb, eb);
#pragma unroll
            for (int j = 0; j < 8; j++){
                Sa[j] = ffma2(ua[j], eda, Sa[j]);
                Sb[j] = ffma2(ub[j], edb, Sb[j]);
            }
        }
        p ^= 1;
    }
    if (cur_c >= 0) flush_S(cur_c, b0, b1, Sa, Sb, Ea, Eb, 1);
}

// ---------------- squash (+ normalization + accumulator re-zero) ----------------
__global__ void __launch_bounds__(128) squash_kernel(float* out, int mode){
    const int c = blockIdx.x;
    const int b = blockIdx.y*128 + threadIdx.x;

    float s[O_];
    float inv;
    if (mode){ inv = 1.0f / g_E[c*B_ + b]; g_E[c*B_ + b] = 0.f; }
    else     { inv = 1.0f / (float)R_; }

    float sq = 0.f;
#pragma unroll
    for (int o = 0; o < O_; o++){
        int sidx = (c*O_ + o)*B_ + b;
        float v = g_S[sidx] * inv;
        g_S[sidx] = 0.f;                  // re-zero for next pass / replay
        s[o] = v;
        sq += v*v;
    }

    float scale = sq / ((1.0f + sq) * sqrtf(sq + 1e-7f));
    float* dst = (out ? out : g_v) + (b*C_ + c)*O_;
    float4* d4 = reinterpret_cast<float4*>(dst);
#pragma unroll
    for (int q = 0; q < 4; q++)
        d4[q] = make_float4(s[4*q]*scale, s[4*q+1]*scale, s[4*q+2]*scale, s[4*q+3]*scale);
}

// ---------------- launch ----------------
extern "C" void kernel_launch(void* const* d_in, const int* in_sizes, int n_in,
                              void* d_out, int out_size){
    const float* x = (const float*)d_in[0];
    const float* W = (const float*)d_in[1];
    if (n_in >= 2 && in_sizes[0] == R_*C_*O_*I_){ const float* t = x; x = W; W = t; }

    prep_kernel<<<PREP_BLOCKS, 256>>>(x, W);   // transpose x, reformat W, zero S/E

    dim3 sq_grid(C_, 2);
    pass0_kernel<<<G0_, 128>>>();
    squash_kernel<<<sq_grid, 128>>>(nullptr, 0);          // v0
    pass_kernel<1><<<G12_, 128>>>();
    squash_kernel<<<sq_grid, 128>>>(nullptr, 1);          // v1
    pass_kernel<2><<<G12_, 128>>>();
    squash_kernel<<<sq_grid, 128>>>((float*)d_out, 1);    // v2 -> output (B,1,C,O,1)
}

// round 11
// speedup vs baseline: 1.0174x; 1.0174x over previous
#include <cuda_runtime.h>
#include <math.h>
#include <stdint.h>

// Problem constants
#define B_ 256
#define R_ 1152
#define C_ 10
#define O_ 16
#define I_ 8
#define RT_ 4                 // r's per tile
#define RPC_ (R_/RT_)         // 288 tiles per c
#define NT_ (RPC_*C_)         // 2880 tiles total
#define G_ 296                // 148 SMs x 2 blocks (256 thr) -> one wave

// smem per buffer: W tile 128 float4 + x tile 2048 float4
#define WF4_ 128
#define XF4_ 2048
#define BUF_F4_ (WF4_ + XF4_)             // 2176 float4
#define SMEM_BYTES (2*BUF_F4_*16)         // 69632 B

// ---------------- device scratch (no allocations allowed) ----------------
__device__ float g_xT[R_*B_*I_];       // x transposed: [r][b][i]
__device__ float g_Wp[R_*C_*I_*O_];    // W reformatted: [r][c][i][o]
__device__ float g_b1[R_*C_*B_];       // b1 logits, tiled: float2 @ (t*RT+rl)*128+bg
__device__ float g_S[C_*O_*B_];        // numerator accumulator: [c][o][b]
__device__ float g_E[C_*B_];           // softmax denominator:   [c][b]
__device__ float g_v[B_*C_*O_];        // squashed v: [b][c][o]

typedef unsigned long long u64;

// ---------------- packed f32x2 helpers ----------------
__device__ __forceinline__ u64 pk2(float lo, float hi){
    u64 r; asm("mov.b64 %0,{%1,%2};" : "=l"(r) : "f"(lo), "f"(hi)); return r;
}
__device__ __forceinline__ void upk2(u64 v, float& lo, float& hi){
    asm("mov.b64 {%0,%1},%2;" : "=f"(lo), "=f"(hi) : "l"(v));
}
__device__ __forceinline__ u64 ffma2(u64 a, u64 b, u64 c){
    u64 d; asm("fma.rn.f32x2 %0,%1,%2,%3;" : "=l"(d) : "l"(a), "l"(b), "l"(c)); return d;
}
__device__ __forceinline__ u64 fadd2(u64 a, u64 b){
    u64 d; asm("add.rn.f32x2 %0,%1,%2;" : "=l"(d) : "l"(a), "l"(b)); return d;
}

// ---------------- cp.async helpers ----------------
__device__ __forceinline__ void cp16(uint32_t s, const void* g){
    asm volatile("cp.async.ca.shared.global [%0], [%1], 16;" :: "r"(s), "l"(g));
}
#define CP_COMMIT() asm volatile("cp.async.commit_group;")
#define CP_WAIT0()  asm volatile("cp.async.wait_group 0;" ::: "memory")

// ---------------- combined prep kernel ----------------
#define XT_BLOCKS 288
#define PREP_BLOCKS (XT_BLOCKS + 720)

__global__ void __launch_bounds__(256) prep_kernel(const float* __restrict__ x,
                                                   const float* __restrict__ W){
    if (blockIdx.x < XT_BLOCKS){
        __shared__ __align__(16) float4 p0[32][33];
        __shared__ __align__(16) float4 p1[32][33];
        const int rt = blockIdx.x >> 3, bt = blockIdx.x & 7;
        const int r0 = rt*32, b0 = bt*32;
        const int w = threadIdx.x >> 5, lane = threadIdx.x & 31;
#pragma unroll
        for (int k = 0; k < 4; k++){
            int bl = w*4 + k;
            const float4* src = reinterpret_cast<const float4*>(
                x + ((b0+bl)*R_ + r0 + lane)*I_);
            p0[bl][lane] = src[0];
            p1[bl][lane] = src[1];
        }
        __syncthreads();
#pragma unroll
        for (int k = 0; k < 4; k++){
            int rl = w*4 + k;
            float4* dst = reinterpret_cast<float4*>(
                g_xT + ((r0+rl)*B_ + b0 + lane)*I_);
            dst[0] = p0[lane][rl];
            dst[1] = p1[lane][rl];
        }
    } else {
        int t = (blockIdx.x - XT_BLOCKS)*256 + threadIdx.x;
        int o = t % O_; int rc = t / O_;
        const float* src = W + t*I_;
        float* dst = g_Wp + rc*(I_*O_);
#pragma unroll
        for (int i = 0; i < I_; i++) dst[i*O_ + o] = src[i];
        if (t < C_*O_*B_) g_S[t] = 0.f;
        if (t < C_*B_)    g_E[t] = 0.f;
    }
}

// ---------------- fused routing pass ----------------
// 256 threads: tid = bg*2 + oh; bg in [0,128), oh in [0,2).
// Thread handles b_k = bg + 128k (k=0,1) and o in [oh*8, oh*8+8).
// MODE 0: S += u_hat
// MODE 1: b1 = <u,v0> (store float2, oh=0 only), S += e*u, E += e (oh=0 only)
// MODE 2: b2 = b1 + <u,v1>,                       S += e*u, E += e (oh=0 only)
template<int MODE>
__global__ void __launch_bounds__(256, 2) pass_kernel(){
    extern __shared__ __align__(16) float4 sm[];
    const int k_  = blockIdx.x;
    const int t0  = (k_    * NT_) / G_;
    const int t1  = ((k_+1)* NT_) / G_;
    const int tid = threadIdx.x;
    const int bg  = tid >> 1, oh = tid & 1;
    const float4* gW4 = reinterpret_cast<const float4*>(g_Wp);
    const float4* gX4 = reinterpret_cast<const float4*>(g_xT);

    uint32_t smbase = (uint32_t)__cvta_generic_to_shared(sm);

    // stage tile t into buffer p: W (128 f4, tid<128) + x (8 f4/thread)
    auto stage = [&](int t, int p){
        int c  = t / RPC_;
        int r0 = (t % RPC_) * RT_;
        uint32_t base = smbase + (uint32_t)p*BUF_F4_*16;
        if (tid < 128)
            cp16(base + tid*16, &gW4[((r0+(tid>>5))*C_ + c)*32 + (tid&31)]);
#pragma unroll
        for (int j = 0; j < 8; j++){
            int f  = tid + j*256;                  // [rl][h][b] layout
            int rl = f >> 9, rem = f & 511;
            int h  = rem >> 8, b = rem & 255;
            cp16(base + (WF4_ + f)*16, &gX4[(((r0+rl)*B_ + b) << 1) + h]);
        }
    };

    u64 u[8], S[8], v[8];
#pragma unroll
    for (int j = 0; j < 8; j++) S[j] = 0ull;
    float E[2] = {0.f, 0.f};
    int cur_c = -1;
    int p = 0;

    if (t0 < t1){ stage(t0, 0); CP_COMMIT(); }

#pragma unroll 1
    for (int t = t0; t < t1; t++){
        const int c  = t / RPC_;

        if (c != cur_c){
            if (cur_c >= 0){
#pragma unroll
                for (int k = 0; k < 2; k++){
                    int b = bg + 128*k;
#pragma unroll
                    for (int q = 0; q < 4; q++){
                        float lo, hi; upk2(S[k*4+q], lo, hi);
                        int o = oh*8 + 2*q;
                        atomicAdd(&g_S[(cur_c*O_ + o    )*B_ + b], lo);
                        atomicAdd(&g_S[(cur_c*O_ + o + 1)*B_ + b], hi);
                        S[k*4+q] = 0ull;
                    }
                    if (MODE && oh == 0){ atomicAdd(&g_E[cur_c*B_ + b], E[k]); E[k] = 0.f; }
                }
            }
            if (MODE){
#pragma unroll
                for (int k = 0; k < 2; k++){
                    const float4* vp = reinterpret_cast<const float4*>(
                        g_v + ((bg + 128*k)*C_ + c)*O_ + oh*8);
                    float4 f0 = vp[0], f1 = vp[1];
                    v[k*4+0] = pk2(f0.x, f0.y); v[k*4+1] = pk2(f0.z, f0.w);
                    v[k*4+2] = pk2(f1.x, f1.y); v[k*4+3] = pk2(f1.z, f1.w);
                }
            }
            cur_c = c;
        }

        CP_WAIT0();
        __syncthreads();
        if (t + 1 < t1){ stage(t+1, p^1); CP_COMMIT(); }

        // prefetch this tile's b1 (MODE 2): one float2 per rl (lane pairs broadcast)
        float2 bq[RT_];
        if (MODE == 2){
#pragma unroll
            for (int rl = 0; rl < RT_; rl++)
                bq[rl] = reinterpret_cast<const float2*>(g_b1)[(t*RT_ + rl)*128 + bg];
        }

        const float4* buf = sm + p*BUF_F4_;
        const float*  Wt  = reinterpret_cast<const float*>(buf);
        const float4* Xt  = buf + WF4_;

#pragma unroll
        for (int rl = 0; rl < RT_; rl++){
            float xs[2][8];
#pragma unroll
            for (int k = 0; k < 2; k++){
                int b = bg + 128*k;
                float4 h0 = Xt[rl*512 + b];
                float4 h1 = Xt[rl*512 + 256 + b];
                xs[k][0]=h0.x; xs[k][1]=h0.y; xs[k][2]=h0.z; xs[k][3]=h0.w;
                xs[k][4]=h1.x; xs[k][5]=h1.y; xs[k][6]=h1.z; xs[k][7]=h1.w;
            }

#pragma unroll
            for (int j = 0; j < 8; j++) u[j] = 0ull;
            const float* wrow = Wt + rl*128 + oh*8;
#pragma unroll
            for (int i = 0; i < I_; i++){
                const ulonglong2* wp = reinterpret_cast<const ulonglong2*>(wrow + i*16);
                ulonglong2 w0 = wp[0];           // o-pairs 0,1 of this half
                u64 w2 = wp[1].x, w3 = wp[1].y;  // o-pairs 2,3
#pragma unroll
                for (int k = 0; k < 2; k++){
                    u64 xd = pk2(xs[k][i], xs[k][i]);
                    u[k*4+0] = ffma2(w0.x, xd, u[k*4+0]);
                    u[k*4+1] = ffma2(w0.y, xd, u[k*4+1]);
                    u[k*4+2] = ffma2(w2,   xd, u[k*4+2]);
                    u[k*4+3] = ffma2(w3,   xd, u[k*4+3]);
                }
            }

            if (MODE == 0){
#pragma unroll
                for (int j = 0; j < 8; j++) S[j] = fadd2(S[j], u[j]);
            } else {
                float tk[2];
#pragma unroll
                for (int k = 0; k < 2; k++){
                    u64 qa = ffma2(u[k*4+0], v[k*4+0], 0ull);
                    u64 qb = ffma2(u[k*4+2], v[k*4+2], 0ull);
                    qa = ffma2(u[k*4+1], v[k*4+1], qa);
                    qb = ffma2(u[k*4+3], v[k*4+3], qb);
                    float lo, hi; upk2(fadd2(qa, qb), lo, hi);
                    float th = lo + hi;
                    tk[k] = th + __shfl_xor_sync(0xffffffffu, th, 1);
                }
                if (MODE == 2){
                    tk[0] += bq[rl].x; tk[1] += bq[rl].y;
                } else if (oh == 0){
                    reinterpret_cast<float2*>(g_b1)[(t*RT_ + rl)*128 + bg] =
                        make_float2(tk[0], tk[1]);
                }
#pragma unroll
                for (int k = 0; k < 2; k++){
                    float e = __expf(tk[k]);
                    if (oh == 0) E[k] += e;       // E counted ONCE per (b,r,c)
                    u64 ed = pk2(e, e);
                    S[k*4+0] = ffma2(u[k*4+0], ed, S[k*4+0]);
                    S[k*4+1] = ffma2(u[k*4+1], ed, S[k*4+1]);
                    S[k*4+2] = ffma2(u[k*4+2], ed, S[k*4+2]);
                    S[k*4+3] = ffma2(u[k*4+3], ed, S[k*4+3]);
                }
            }
        }
        p ^= 1;
    }

    if (cur_c >= 0){
#pragma unroll
        for (int k = 0; k < 2; k++){
            int b = bg + 128*k;
#pragma unroll
            for (int q = 0; q < 4; q++){
                float lo, hi; upk2(S[k*4+q], lo, hi);
                int o = oh*8 + 2*q;
                atomicAdd(&g_S[(cur_c*O_ + o    )*B_ + b], lo);
                atomicAdd(&g_S[(cur_c*O_ + o + 1)*B_ + b], hi);
            }
            if (MODE && oh == 0) atomicAdd(&g_E[cur_c*B_ + b], E[k]);
        }
    }
}

// ---------------- squash (+ normalization + accumulator re-zero) ----------------
__global__ void __launch_bounds__(128) squash_kernel(float* out, int mode){
    const int c = blockIdx.x;
    const int b = blockIdx.y*128 + threadIdx.x;

    float s[O_];
    float inv;
    if (mode){ inv = 1.0f / g_E[c*B_ + b]; g_E[c*B_ + b] = 0.f; }
    else     { inv = 1.0f / (float)R_; }

    float sq = 0.f;
#pragma unroll
    for (int o = 0; o < O_; o++){
        int sidx = (c*O_ + o)*B_ + b;
        float v = g_S[sidx] * inv;
        g_S[sidx] = 0.f;
        s[o] = v;
        sq += v*v;
    }

    float scale = sq / ((1.0f + sq) * sqrtf(sq + 1e-7f));
    float* dst = (out ? out : g_v) + (b*C_ + c)*O_;
    float4* d4 = reinterpret_cast<float4*>(dst);
#pragma unroll
    for (int q = 0; q < 4; q++)
        d4[q] = make_float4(s[4*q]*scale, s[4*q+1]*scale, s[4*q+2]*scale, s[4*q+3]*scale);
}

// ---------------- launch ----------------
extern "C" void kernel_launch(void* const* d_in, const int* in_sizes, int n_in,
                              void* d_out, int out_size){
    const float* x = (const float*)d_in[0];
    const float* W = (const float*)d_in[1];
    if (n_in >= 2 && in_sizes[0] == R_*C_*O_*I_){ const float* t = x; x = W; W = t; }

    cudaFuncSetAttribute(pass_kernel<0>, cudaFuncAttributeMaxDynamicSharedMemorySize, SMEM_BYTES);
    cudaFuncSetAttribute(pass_kernel<1>, cudaFuncAttributeMaxDynamicSharedMemorySize, SMEM_BYTES);
    cudaFuncSetAttribute(pass_kernel<2>, cudaFuncAttributeMaxDynamicSharedMemorySize, SMEM_BYTES);

    prep_kernel<<<PREP_BLOCKS, 256>>>(x, W);

    dim3 sq_grid(C_, 2);
    pass_kernel<0><<<G_, 256, SMEM_BYTES>>>();
    squash_kernel<<<sq_grid, 128>>>(nullptr, 0);          // v0
    pass_kernel<1><<<G_, 256, SMEM_BYTES>>>();
    squash_kernel<<<sq_grid, 128>>>(nullptr, 1);          // v1
    pass_kernel<2><<<G_, 256, SMEM_BYTES>>>();
    squash_kernel<<<sq_grid, 128>>>((float*)d_out, 1);    // v2 -> output (B,1,C,O,1)
}